// round 5
// baseline (speedup 1.0000x reference)
#include <cuda_runtime.h>
#include <cstdint>

#define ALPHA_LRELU 0.8f
#define NODES_PER_BLOCK 16
#define NTHREADS 256
#define WT_STRIDE 132   // 128 + 4 pad: conflict-free LDS.128 column reads

// f32x2 packed math (Blackwell FFMA2 path — only reachable via PTX).
#define FMA2(d, a, b, c) \
    asm("fma.rn.f32x2 %0, %1, %2, %3;" : "=l"(d) : "l"(a), "l"(b), "l"(c))
#define MUL2(d, a, b) \
    asm("mul.rn.f32x2 %0, %1, %2;" : "=l"(d) : "l"(a), "l"(b))

__device__ __forceinline__ uint64_t pack2(float lo, float hi) {
    uint64_t r; asm("mov.b64 %0, {%1, %2};" : "=l"(r) : "f"(lo), "f"(hi)); return r;
}
__device__ __forceinline__ float2 unpack2(uint64_t v) {
    float2 r; asm("mov.b64 {%0, %1}, %2;" : "=f"(r.x), "=f"(r.y) : "l"(v)); return r;
}
__device__ __forceinline__ uint64_t d2l(double d) { return __double_as_longlong(d); }

// Scratch for precomputed score-projection vectors (no allocs allowed).
__device__ __align__(16) float g_c1[128];   // W  @ a_x
__device__ __align__(16) float g_c2[128];   // W2 @ a_n

__global__ void precompute_kernel(const float* __restrict__ W,
                                  const float* __restrict__ W2,
                                  const float* __restrict__ a) {
    int k = threadIdx.x;  // 0..127
    float s1 = 0.f, s2 = 0.f;
#pragma unroll
    for (int d = 0; d < 64; ++d) {
        s1 += W [k * 64 + d] * a[d];
        s2 += W2[k * 64 + d] * a[64 + d];
    }
    g_c1[k] = s1;
    g_c2[k] = s2;
}

__device__ __forceinline__ float warp_sum(float v) {
    v += __shfl_xor_sync(0xffffffffu, v, 16);
    v += __shfl_xor_sync(0xffffffffu, v, 8);
    v += __shfl_xor_sync(0xffffffffu, v, 4);
    v += __shfl_xor_sync(0xffffffffu, v, 2);
    v += __shfl_xor_sync(0xffffffffu, v, 1);
    return v;
}

// Phase A (warp == node, 2 nodes/warp/tile): attention (online softmax) +
//   raw-feature aggregation, packed f32x2 updates.
// Phase B (block-wide): [16 x 128] @ (W | W2) with W^T/W2^T in padded smem.
//   Thread owns 1 output column x 8 nodes; k-pairs packed into FFMA2.
__global__ __launch_bounds__(NTHREADS, 2)
void gat_fused_kernel(const float* __restrict__ input,
                      const float* __restrict__ neigh,
                      const float* __restrict__ edge,
                      const float* __restrict__ W,
                      const float* __restrict__ W2,
                      const float* __restrict__ a,
                      float* __restrict__ out,
                      int N) {
    extern __shared__ float sh[];
    float* Wt   = sh;                       // 64 x WT_STRIDE (W^T, padded)
    float* W2t  = sh + 64 * WT_STRIDE;      // 64 x WT_STRIDE
    float* in_sh  = sh + 2 * 64 * WT_STRIDE;                  // 16*128
    float* agg_sh = sh + 2 * 64 * WT_STRIDE + NODES_PER_BLOCK * 128;

    const int tid = threadIdx.x;
    // Cooperative transposed weight load (once per persistent block).
    for (int i = tid; i < 2048; i += NTHREADS) {
        const int k  = i >> 4;          // 0..127
        const int d0 = (i & 15) * 4;
        const float4 w4  = ((const float4*)W)[i];
        const float4 w24 = ((const float4*)W2)[i];
        Wt [(d0 + 0) * WT_STRIDE + k] = w4.x;
        Wt [(d0 + 1) * WT_STRIDE + k] = w4.y;
        Wt [(d0 + 2) * WT_STRIDE + k] = w4.z;
        Wt [(d0 + 3) * WT_STRIDE + k] = w4.w;
        W2t[(d0 + 0) * WT_STRIDE + k] = w24.x;
        W2t[(d0 + 1) * WT_STRIDE + k] = w24.y;
        W2t[(d0 + 2) * WT_STRIDE + k] = w24.z;
        W2t[(d0 + 3) * WT_STRIDE + k] = w24.w;
    }
    __syncthreads();

    const int w = tid >> 5;        // warp id
    const int l = tid & 31;        // lane

    const double2 c1d = ((const double2*)g_c1)[l];
    const double2 c2d = ((const double2*)g_c2)[l];
    const uint64_t c1a = d2l(c1d.x), c1b = d2l(c1d.y);
    const uint64_t c2a = d2l(c2d.x), c2b = d2l(c2d.y);
    const float  aev = a[128 + l];          // a_e[l]

    // Phase-B mapping: each thread owns one output column for 8 nodes.
    const int col  = tid & 127;             // 0..127
    const int r0   = (tid >> 7) * 8;        // rows r0..r0+7 of this block's 16
    const int c    = col & 63;
    const float* Mrow = ((col < 64) ? Wt   : W2t) + c * WT_STRIDE;
    const float* srcS = (col < 64) ? in_sh : agg_sh;

    for (int n0 = blockIdx.x * NODES_PER_BLOCK; n0 < N;
         n0 += gridDim.x * NODES_PER_BLOCK) {

        // ---- Phase A: 2 nodes per warp (rows w and w+8) ----
#pragma unroll
        for (int j = 0; j < 2; ++j) {
            const int row = j * 8 + w;
            const int n = n0 + row;
            if (n < N) {
                const double2 in2 = ((const double2*)(input + (long long)n * 128))[l];
                ((double2*)(in_sh + row * 128))[l] = in2;
                const uint64_t i01 = d2l(in2.x), i23 = d2l(in2.y);
                uint64_t sdot;
                MUL2(sdot, i01, c1a);
                FMA2(sdot, i23, c1b, sdot);
                const float2 su = unpack2(sdot);
                const float sx = warp_sum(su.x + su.y);

                const double2* nrow = (const double2*)(neigh + (long long)n * 2048);
                const float*   erow = edge + (long long)n * 512;

                float m = -1e30f, sum = 0.f, agge = 0.f;
                uint64_t agg01 = 0ull, agg23 = 0ull;   // (0.f, 0.f) bit pattern
#pragma unroll
                for (int s = 0; s < 16; ++s) {
                    const double2 v2 = nrow[s * 32 + l];
                    const uint64_t v01 = d2l(v2.x), v23 = d2l(v2.y);
                    const float e = erow[s * 32 + l];
                    uint64_t q2;
                    MUL2(q2, v01, c2a);
                    FMA2(q2, v23, c2b, q2);
                    const float2 qu = unpack2(q2);
                    const float q = warp_sum(qu.x + qu.y + e * aev);
                    float t = sx + q;
                    t = (t > 0.f) ? t : ALPHA_LRELU * t;
                    const float m_new = fmaxf(m, t);
                    const float scale = __expf(m - m_new);
                    const float p     = __expf(t - m_new);
                    const uint64_t sc2 = pack2(scale, scale);
                    const uint64_t p2  = pack2(p, p);
                    uint64_t t01, t23;
                    MUL2(t01, p2, v01);
                    FMA2(agg01, agg01, sc2, t01);
                    MUL2(t23, p2, v23);
                    FMA2(agg23, agg23, sc2, t23);
                    sum  = sum * scale + p;
                    agge = agge * scale + p * e;
                    m = m_new;
                }
                const float inv = 1.f / sum;
                const uint64_t inv2 = pack2(inv, inv);
                MUL2(agg01, agg01, inv2);
                MUL2(agg23, agg23, inv2);
                ((double2*)(agg_sh + row * 128))[l] =
                    make_double2(__longlong_as_double((long long)agg01),
                                 __longlong_as_double((long long)agg23));
                out[(long long)n * 160 + 128 + l] = agge * inv;   // h_edge
            }
        }
        __syncthreads();

        // ---- Phase B: block-wide GEMV, 8 nodes/thread, FFMA2 k-pairs ----
        uint64_t acc01[8], acc23[8];
#pragma unroll
        for (int j = 0; j < 8; ++j) { acc01[j] = 0ull; acc23[j] = 0ull; }

        const double2* m2 = (const double2*)Mrow;
#pragma unroll 4
        for (int k = 0; k < 32; ++k) {
            const double2 wk = m2[k];
            const uint64_t w01 = d2l(wk.x), w23 = d2l(wk.y);
#pragma unroll
            for (int j = 0; j < 8; ++j) {
                const double2 sj = ((const double2*)(srcS + (r0 + j) * 128))[k];
                FMA2(acc01[j], w01, d2l(sj.x), acc01[j]);
                FMA2(acc23[j], w23, d2l(sj.y), acc23[j]);
            }
        }
#pragma unroll
        for (int j = 0; j < 8; ++j) {
            const int nn = n0 + r0 + j;
            if (nn < N) {
                const float2 u = unpack2(acc01[j]);
                const float2 v = unpack2(acc23[j]);
                out[(long long)nn * 160 + col] = (u.x + u.y) + (v.x + v.y);
            }
        }
        __syncthreads();  // protect in_sh/agg_sh before next iteration
    }
}

extern "C" void kernel_launch(void* const* d_in, const int* in_sizes, int n_in,
                              void* d_out, int out_size) {
    const float* input = (const float*)d_in[0];
    const float* neigh = (const float*)d_in[1];
    const float* edge  = (const float*)d_in[2];
    const float* W     = (const float*)d_in[3];
    const float* W2    = (const float*)d_in[4];
    const float* a     = (const float*)d_in[5];
    float* out = (float*)d_out;

    const int N = in_sizes[0] / 128;

    const int smem_bytes = (2 * 64 * WT_STRIDE + NODES_PER_BLOCK * 128 * 2) * 4;
    cudaFuncSetAttribute(gat_fused_kernel,
                         cudaFuncAttributeMaxDynamicSharedMemorySize, smem_bytes);

    precompute_kernel<<<1, 128>>>(W, W2, a);
    gat_fused_kernel<<<296, NTHREADS, smem_bytes>>>(input, neigh, edge, W, W2, a,
                                                    out, N);
}